// round 10
// baseline (speedup 1.0000x reference)
#include <cuda_runtime.h>
#include <cuda_bf16.h>

#define SEQ   4096
#define BATCH 256
#define DIN   64
#define DH    128

// Scratch for precomputed input projections x_proj[s][b][j].
__device__ float g_xproj[SEQ * BATCH * DH];

// ---------------------------------------------------------------------------
// Packed fp32x2 helpers (Blackwell: 2 FMAs per instruction, rt=2/SMSP).
// ---------------------------------------------------------------------------
__device__ __forceinline__ unsigned long long pack2(float lo, float hi) {
    unsigned long long r;
    asm("mov.b64 %0, {%1, %2};" : "=l"(r) : "f"(lo), "f"(hi));
    return r;
}

__device__ __forceinline__ float2 unpack2(unsigned long long v) {
    float2 f;
    asm("mov.b64 {%0, %1}, %2;" : "=f"(f.x), "=f"(f.y) : "l"(v));
    return f;
}

__device__ __forceinline__ void ffma2(unsigned long long& d,
                                      unsigned long long a,
                                      unsigned long long b) {
    asm("fma.rn.f32x2 %0, %1, %2, %0;" : "+l"(d) : "l"(a), "l"(b));
}

__device__ __forceinline__ unsigned long long fadd2(unsigned long long a,
                                                    unsigned long long b) {
    unsigned long long d;
    asm("add.rn.f32x2 %0, %1, %2;" : "=l"(d) : "l"(a), "l"(b));
    return d;
}

// tanh via 2x MUFU (EX2 + RCP), rel err ~2^-20 (tanh.approx's ~5e-4 would
// risk the 1e-3 gate after 4096-step accumulation; this keeps ~3e-7).
__device__ __forceinline__ float fast_tanh(float x) {
    float e = __expf(x + x);
    return 1.0f - __fdividef(2.0f, e + 1.0f);
}

// ---------------------------------------------------------------------------
// Phase 1: x_proj[s,b,j] = dot(input[s,b,:], W_ih[j,:]) + b_ih[j] + b_hh[j]
// ---------------------------------------------------------------------------
__global__ void __launch_bounds__(128) xproj_kernel(
    const float* __restrict__ in,     // [SEQ*BATCH, DIN]
    const float* __restrict__ Wih,    // [DH, DIN]
    const float* __restrict__ bA,
    const float* __restrict__ bB)
{
    __shared__ __align__(16) float sin_t[16][DIN];   // 4 KB tile

    const int j = threadIdx.x;

    unsigned long long wp[32];
#pragma unroll
    for (int q = 0; q < 16; q++) {
        float4 v = *(const float4*)(Wih + j * DIN + q * 4);
        wp[2 * q]     = pack2(v.x, v.y);
        wp[2 * q + 1] = pack2(v.z, v.w);
    }
    const float bias = bA[j] + bB[j];

    const int ntiles = (SEQ * BATCH) / 16;
    for (int tile = blockIdx.x; tile < ntiles; tile += gridDim.x) {
        __syncthreads();   // WAR on sin_t reuse
        const float4* src = (const float4*)(in + tile * (16 * DIN));
        ((float4*)&sin_t[0][0])[j]       = src[j];
        ((float4*)&sin_t[0][0])[128 + j] = src[128 + j];
        __syncthreads();

        for (int r = 0; r < 16; r++) {
            unsigned long long acc[4] = {0ULL, 0ULL, 0ULL, 0ULL};
#pragma unroll
            for (int q = 0; q < 16; q++) {
                ulonglong2 hv = *(const ulonglong2*)&sin_t[r][q * 4];
                ffma2(acc[(q & 1) * 2],     wp[2 * q],     hv.x);
                ffma2(acc[(q & 1) * 2 + 1], wp[2 * q + 1], hv.y);
            }
            unsigned long long t = fadd2(fadd2(acc[0], acc[1]),
                                         fadd2(acc[2], acc[3]));
            float2 f = unpack2(t);
            __stcs(&g_xproj[(tile * 16 + r) * DH + j], f.x + f.y + bias);
        }
    }
}

// ---------------------------------------------------------------------------
// Phase 2: sequential scan. 128 blocks x 128 threads, TWO batch rows/block,
// both rows computed IN THE SAME THREAD:
//   - thread j owns output unit j for rows {2b, 2b+1}; the single
//     register-resident W_hh row j (128 regs) feeds both dot products
//   - the two rows' FFMA2 chains interleave in the instruction stream ->
//     guaranteed ILP (8 independent chains) instead of relying on the
//     arbiter to de-phase two identical CTAs (R5-R8's failure mode)
//   - two independent tanh tails pipeline through MUFU; one barrier per
//     step covers both rows
//   - grid=128 <= 148 SMs: every CTA gets its own SM, no phase-locking
// ---------------------------------------------------------------------------
__device__ __forceinline__ void scan_step2(
    const float* __restrict__ hA, const float* __restrict__ hB,
    const unsigned long long* __restrict__ wp,
    float xa, float xb, float& oa, float& ob)
{
    unsigned long long aA[4] = {0ULL, 0ULL, 0ULL, 0ULL};
    unsigned long long aB[4] = {0ULL, 0ULL, 0ULL, 0ULL};
#pragma unroll
    for (int q = 0; q < 32; q++) {               // LDS.128 broadcast x2
        ulonglong2 pA = *(const ulonglong2*)(hA + q * 4);
        ulonglong2 pB = *(const ulonglong2*)(hB + q * 4);
        ffma2(aA[(2 * q)     & 3], wp[2 * q],     pA.x);
        ffma2(aB[(2 * q)     & 3], wp[2 * q],     pB.x);
        ffma2(aA[(2 * q + 1) & 3], wp[2 * q + 1], pA.y);
        ffma2(aB[(2 * q + 1) & 3], wp[2 * q + 1], pB.y);
    }
    unsigned long long uA = fadd2(fadd2(aA[0], aA[1]), fadd2(aA[2], aA[3]));
    unsigned long long uB = fadd2(fadd2(aB[0], aB[1]), fadd2(aB[2], aB[3]));
    float2 fA = unpack2(uA), fB = unpack2(uB);
    oa = fast_tanh(xa + (fA.x + fA.y));
    ob = fast_tanh(xb + (fB.x + fB.y));
}

__global__ void __launch_bounds__(128, 1) rnn_scan_kernel(
    const float* __restrict__ Whh,    // [DH, DH]
    float* __restrict__ out)          // [BATCH, DH]
{
    const int j    = threadIdx.x;     // output unit 0..127
    const int rowA = blockIdx.x * 2;  // this CTA's two batch rows
    const int rowB = rowA + 1;

    __shared__ __align__(16) float hA0[DH], hA1[DH];
    __shared__ __align__(16) float hB0[DH], hB1[DH];

    // Full W_hh row j: 64 packed f32x2 pairs (128 registers), shared by
    // both rows' dot products.
    unsigned long long wp[64];
#pragma unroll
    for (int q = 0; q < 32; q++) {
        float4 v = *(const float4*)(Whh + j * DH + q * 4);
        wp[2 * q]     = pack2(v.x, v.y);
        wp[2 * q + 1] = pack2(v.z, v.w);
    }

    hA0[j] = 0.0f;                    // h0 = 0
    hB0[j] = 0.0f;

    const float* xA = &g_xproj[rowA * DH + j];
    const float* xB = &g_xproj[rowB * DH + j];
    const int STRIDE = BATCH * DH;

    // Distance-2 prefetch (streaming: x_proj is single-use).
    float xcA = __ldcs(xA);               float xcB = __ldcs(xB);
    float xnA = __ldcs(xA + STRIDE);      float xnB = __ldcs(xB + STRIDE);

    __syncthreads();

    float hAv = 0.0f, hBv = 0.0f;
    for (int s = 0; s < SEQ; s += 2) {
        // --- even step: read buf0, write buf1 ---
        const size_t o0 = (size_t)min(s + 2, SEQ - 1) * STRIDE;
        float xfA = __ldcs(xA + o0), xfB = __ldcs(xB + o0);
        scan_step2(hA0, hB0, wp, xcA, xcB, hAv, hBv);
        hA1[j] = hAv; hB1[j] = hBv;
        xcA = xnA; xnA = xfA; xcB = xnB; xnB = xfB;
        __syncthreads();

        // --- odd step: read buf1, write buf0 ---
        const size_t o1 = (size_t)min(s + 3, SEQ - 1) * STRIDE;
        float xgA = __ldcs(xA + o1), xgB = __ldcs(xB + o1);
        scan_step2(hA1, hB1, wp, xcA, xcB, hAv, hBv);
        hA0[j] = hAv; hB0[j] = hBv;
        xcA = xnA; xnA = xgA; xcB = xnB; xnB = xgB;
        __syncthreads();
    }

    out[rowA * DH + j] = hAv;
    out[rowB * DH + j] = hBv;
}

// ---------------------------------------------------------------------------
// Launch.
// ---------------------------------------------------------------------------
extern "C" void kernel_launch(void* const* d_in, const int* in_sizes, int n_in,
                              void* d_out, int out_size) {
    const float* input = nullptr;
    const float* Wih   = nullptr;
    const float* Whh   = nullptr;
    const float* bA    = nullptr;
    const float* bB    = nullptr;

    for (int i = 0; i < n_in; i++) {
        const int sz = in_sizes[i];
        const float* p = (const float*)d_in[i];
        if      (sz == SEQ * BATCH * DIN) input = p;
        else if (sz == DH * DIN)          Wih   = p;
        else if (sz == DH * DH)           Whh   = p;
        else if (sz == DH)                { if (!bA) bA = p; else bB = p; }
    }

    xproj_kernel<<<2048, 128>>>(input, Wih, bA, bB);
    rnn_scan_kernel<<<BATCH / 2, 128>>>(Whh, (float*)d_out);
}

// round 12
// speedup vs baseline: 1.1573x; 1.1573x over previous
#include <cuda_runtime.h>
#include <cuda_bf16.h>

#define SEQ   4096
#define BATCH 256
#define DIN   64
#define DH    128

// Scratch for precomputed input projections x_proj[s][b][j].
__device__ float g_xproj[SEQ * BATCH * DH];

// ---------------------------------------------------------------------------
// Packed fp32x2 helpers (Blackwell: 2 FMAs per instruction, rt=2/SMSP).
// ---------------------------------------------------------------------------
__device__ __forceinline__ unsigned long long pack2(float lo, float hi) {
    unsigned long long r;
    asm("mov.b64 %0, {%1, %2};" : "=l"(r) : "f"(lo), "f"(hi));
    return r;
}

__device__ __forceinline__ float2 unpack2(unsigned long long v) {
    float2 f;
    asm("mov.b64 {%0, %1}, %2;" : "=f"(f.x), "=f"(f.y) : "l"(v));
    return f;
}

__device__ __forceinline__ void ffma2(unsigned long long& d,
                                      unsigned long long a,
                                      unsigned long long b) {
    asm("fma.rn.f32x2 %0, %1, %2, %0;" : "+l"(d) : "l"(a), "l"(b));
}

__device__ __forceinline__ unsigned long long fadd2(unsigned long long a,
                                                    unsigned long long b) {
    unsigned long long d;
    asm("add.rn.f32x2 %0, %1, %2;" : "=l"(d) : "l"(a), "l"(b));
    return d;
}

// tanh via 2x MUFU (EX2 + RCP), rel err ~2^-20 (tanh.approx's ~5e-4 would
// accumulate past the 1e-3 gate over 4096 steps; this keeps ~3e-7).
__device__ __forceinline__ float fast_tanh(float x) {
    float e = __expf(x + x);
    return 1.0f - __fdividef(2.0f, e + 1.0f);
}

// ---------------------------------------------------------------------------
// Phase 1: x_proj[s,b,j] = dot(input[s,b,:], W_ih[j,:]) + b_ih[j] + b_hh[j]
// Double-buffered smem tiles: LDG of tile t+1 overlaps compute of tile t;
// ONE __syncthreads per tile (WAR on a buffer is separated by the sync of
// the intervening iteration).
// ---------------------------------------------------------------------------
__global__ void __launch_bounds__(128) xproj_kernel(
    const float* __restrict__ in,     // [SEQ*BATCH, DIN]
    const float* __restrict__ Wih,    // [DH, DIN]
    const float* __restrict__ bA,
    const float* __restrict__ bB)
{
    __shared__ __align__(16) float sbuf[2][16 * DIN];   // 2 x 4 KB tiles

    const int j = threadIdx.x;

    unsigned long long wp[32];
#pragma unroll
    for (int q = 0; q < 16; q++) {
        float4 v = *(const float4*)(Wih + j * DIN + q * 4);
        wp[2 * q]     = pack2(v.x, v.y);
        wp[2 * q + 1] = pack2(v.z, v.w);
    }
    const float bias = bA[j] + bB[j];

    const int ntiles = (SEQ * BATCH) / 16;
    int tile = blockIdx.x;

    // Register prefetch of the first tile (2 float4 per thread).
    float4 r0, r1;
    if (tile < ntiles) {
        const float4* src = (const float4*)(in + tile * (16 * DIN));
        r0 = src[j];
        r1 = src[128 + j];
    }

    int p = 0;
    for (; tile < ntiles; tile += gridDim.x) {
        // Publish the prefetched tile, then immediately start the next LDG.
        ((float4*)sbuf[p])[j]       = r0;
        ((float4*)sbuf[p])[128 + j] = r1;
        __syncthreads();

        const int next = tile + gridDim.x;
        if (next < ntiles) {
            const float4* src = (const float4*)(in + next * (16 * DIN));
            r0 = src[j];
            r1 = src[128 + j];
        }

        const float* tb = sbuf[p];
        float* dst = &g_xproj[tile * (16 * DH) + j];
#pragma unroll 4
        for (int r = 0; r < 16; r++) {
            unsigned long long acc[4] = {0ULL, 0ULL, 0ULL, 0ULL};
#pragma unroll
            for (int q = 0; q < 16; q++) {
                ulonglong2 hv = *(const ulonglong2*)(tb + r * DIN + q * 4);
                ffma2(acc[(q & 1) * 2],     wp[2 * q],     hv.x);
                ffma2(acc[(q & 1) * 2 + 1], wp[2 * q + 1], hv.y);
            }
            unsigned long long t = fadd2(fadd2(acc[0], acc[1]),
                                         fadd2(acc[2], acc[3]));
            float2 f = unpack2(t);
            __stcs(dst + r * DH, f.x + f.y + bias);
        }
        p ^= 1;
    }
}

// ---------------------------------------------------------------------------
// Phase 2: sequential scan. 256 blocks x 128 threads, one row per block,
// 2 CTAs/SM (R8 chassis — best so far). Thread j owns output unit j with
// the full k=128 dot product; W_hh row j register-resident.
//
// The 32 LDS.128 of h are software-pipelined through a 3-slot register
// ring (groups of 4 loads, prefetch distance 2 groups = ~32 FFMA2-cycles >
// 29-cycle LDS latency), so the load latency is covered by construction
// instead of relying on ptxas lookahead under 200+ live registers.
// ---------------------------------------------------------------------------
__device__ __forceinline__ float scan_step(
    const float* __restrict__ h,                 // smem, current h (128)
    const unsigned long long* __restrict__ wp,   // 64 packed W pairs
    float x)
{
    const ulonglong2* hv = (const ulonglong2*)h;  // 32 x (4 floats)

    unsigned long long acc[8] = {0ULL,0ULL,0ULL,0ULL,0ULL,0ULL,0ULL,0ULL};
    ulonglong2 ring[3][4];                        // 3-slot ring, 4 loads/slot

#pragma unroll
    for (int i = 0; i < 4; i++) ring[0][i] = hv[i];        // group 0
#pragma unroll
    for (int i = 0; i < 4; i++) ring[1][i] = hv[4 + i];    // group 1

#pragma unroll
    for (int g = 0; g < 8; g++) {                 // 8 groups of 16 floats
        if (g + 2 < 8) {                          // prefetch group g+2
#pragma unroll
            for (int i = 0; i < 4; i++)
                ring[(g + 2) % 3][i] = hv[4 * (g + 2) + i];
        }
#pragma unroll
        for (int i = 0; i < 4; i++) {             // consume group g
            ffma2(acc[(2 * i)     & 7], wp[8 * g + 2 * i],     ring[g % 3][i].x);
            ffma2(acc[(2 * i + 1) & 7], wp[8 * g + 2 * i + 1], ring[g % 3][i].y);
        }
    }

    unsigned long long t0 = fadd2(acc[0], acc[1]);
    unsigned long long t1 = fadd2(acc[2], acc[3]);
    unsigned long long t2 = fadd2(acc[4], acc[5]);
    unsigned long long t3 = fadd2(acc[6], acc[7]);
    unsigned long long u  = fadd2(fadd2(t0, t1), fadd2(t2, t3));
    float2 f = unpack2(u);
    return fast_tanh(x + (f.x + f.y));
}

__global__ void __launch_bounds__(128, 2) rnn_scan_kernel(
    const float* __restrict__ Whh,    // [DH, DH]
    float* __restrict__ out)          // [BATCH, DH]
{
    const int j   = threadIdx.x;      // output unit 0..127
    const int row = blockIdx.x;
    const int STRIDE = BATCH * DH;

    __shared__ __align__(16) float h0buf[DH];
    __shared__ __align__(16) float h1buf[DH];

    // Full W_hh row j: 64 packed f32x2 pairs (128 registers).
    unsigned long long wp[64];
#pragma unroll
    for (int q = 0; q < 32; q++) {
        float4 v = *(const float4*)(Whh + j * DH + q * 4);
        wp[2 * q]     = pack2(v.x, v.y);
        wp[2 * q + 1] = pack2(v.z, v.w);
    }

    h0buf[j] = 0.0f;                  // h0 = 0

    const float* xcol = &g_xproj[row * DH + j];
    // Distance-2 prefetch with a rolling pointer (no per-step size_t mul).
    float xc = __ldcs(xcol);
    float xn = __ldcs(xcol + STRIDE);
    const float* xp = xcol + 2 * STRIDE;

    __syncthreads();

    float hn = 0.0f;
    for (int s = 0; s < SEQ; s += 2) {
        // --- even step: read h0buf, write h1buf ---
        float xf0 = (s + 2 < SEQ) ? __ldcs(xp) : 0.0f;
        hn = scan_step(h0buf, wp, xc);
        h1buf[j] = hn;
        xc = xn; xn = xf0;
        __syncthreads();

        // --- odd step: read h1buf, write h0buf ---
        float xf1 = (s + 3 < SEQ) ? __ldcs(xp + STRIDE) : 0.0f;
        hn = scan_step(h1buf, wp, xc);
        h0buf[j] = hn;
        xc = xn; xn = xf1;
        xp += 2 * STRIDE;
        __syncthreads();
    }

    out[row * DH + j] = hn;
}

// ---------------------------------------------------------------------------
// Launch.
// ---------------------------------------------------------------------------
extern "C" void kernel_launch(void* const* d_in, const int* in_sizes, int n_in,
                              void* d_out, int out_size) {
    const float* input = nullptr;
    const float* Wih   = nullptr;
    const float* Whh   = nullptr;
    const float* bA    = nullptr;
    const float* bB    = nullptr;

    for (int i = 0; i < n_in; i++) {
        const int sz = in_sizes[i];
        const float* p = (const float*)d_in[i];
        if      (sz == SEQ * BATCH * DIN) input = p;
        else if (sz == DH * DIN)          Wih   = p;
        else if (sz == DH * DH)           Whh   = p;
        else if (sz == DH)                { if (!bA) bA = p; else bB = p; }
    }

    xproj_kernel<<<2048, 128>>>(input, Wih, bA, bB);
    rnn_scan_kernel<<<BATCH, 128>>>(Whh, (float*)d_out);
}

// round 13
// speedup vs baseline: 1.2314x; 1.0640x over previous
#include <cuda_runtime.h>
#include <cuda_bf16.h>

#define SEQ   4096
#define BATCH 256
#define DIN   64
#define DH    128

// Scratch for precomputed input projections x_proj[s][b][j].
__device__ float g_xproj[SEQ * BATCH * DH];

// ---------------------------------------------------------------------------
// Packed fp32x2 helpers (Blackwell: 2 FMAs per instruction, rt=2/SMSP).
// ---------------------------------------------------------------------------
__device__ __forceinline__ unsigned long long pack2(float lo, float hi) {
    unsigned long long r;
    asm("mov.b64 %0, {%1, %2};" : "=l"(r) : "f"(lo), "f"(hi));
    return r;
}

__device__ __forceinline__ float2 unpack2(unsigned long long v) {
    float2 f;
    asm("mov.b64 {%0, %1}, %2;" : "=f"(f.x), "=f"(f.y) : "l"(v));
    return f;
}

__device__ __forceinline__ void ffma2(unsigned long long& d,
                                      unsigned long long a,
                                      unsigned long long b) {
    asm("fma.rn.f32x2 %0, %1, %2, %0;" : "+l"(d) : "l"(a), "l"(b));
}

__device__ __forceinline__ unsigned long long fadd2(unsigned long long a,
                                                    unsigned long long b) {
    unsigned long long d;
    asm("add.rn.f32x2 %0, %1, %2;" : "=l"(d) : "l"(a), "l"(b));
    return d;
}

// tanh via 2x MUFU (EX2 + RCP), rel err ~2^-20 (tanh.approx's ~5e-4 would
// accumulate past the 1e-3 gate over 4096 steps; this keeps ~3e-7).
__device__ __forceinline__ float fast_tanh(float x) {
    float e = __expf(x + x);
    return 1.0f - __fdividef(2.0f, e + 1.0f);
}

// ---------------------------------------------------------------------------
// Phase 1: x_proj[s,b,j] = dot(input[s,b,:], W_ih[j,:]) + b_ih[j] + b_hh[j]
// Double-buffered smem tiles; one __syncthreads per tile.
// ---------------------------------------------------------------------------
__global__ void __launch_bounds__(128) xproj_kernel(
    const float* __restrict__ in,     // [SEQ*BATCH, DIN]
    const float* __restrict__ Wih,    // [DH, DIN]
    const float* __restrict__ bA,
    const float* __restrict__ bB)
{
    __shared__ __align__(16) float sbuf[2][16 * DIN];   // 2 x 4 KB tiles

    const int j = threadIdx.x;

    unsigned long long wp[32];
#pragma unroll
    for (int q = 0; q < 16; q++) {
        float4 v = *(const float4*)(Wih + j * DIN + q * 4);
        wp[2 * q]     = pack2(v.x, v.y);
        wp[2 * q + 1] = pack2(v.z, v.w);
    }
    const float bias = bA[j] + bB[j];

    const int ntiles = (SEQ * BATCH) / 16;
    int tile = blockIdx.x;

    float4 r0, r1;
    if (tile < ntiles) {
        const float4* src = (const float4*)(in + tile * (16 * DIN));
        r0 = src[j];
        r1 = src[128 + j];
    }

    int p = 0;
    for (; tile < ntiles; tile += gridDim.x) {
        ((float4*)sbuf[p])[j]       = r0;
        ((float4*)sbuf[p])[128 + j] = r1;
        __syncthreads();

        const int next = tile + gridDim.x;
        if (next < ntiles) {
            const float4* src = (const float4*)(in + next * (16 * DIN));
            r0 = src[j];
            r1 = src[128 + j];
        }

        const float* tb = sbuf[p];
        float* dst = &g_xproj[tile * (16 * DH) + j];
#pragma unroll 4
        for (int r = 0; r < 16; r++) {
            unsigned long long acc[4] = {0ULL, 0ULL, 0ULL, 0ULL};
#pragma unroll
            for (int q = 0; q < 16; q++) {
                ulonglong2 hv = *(const ulonglong2*)(tb + r * DIN + q * 4);
                ffma2(acc[(q & 1) * 2],     wp[2 * q],     hv.x);
                ffma2(acc[(q & 1) * 2 + 1], wp[2 * q + 1], hv.y);
            }
            unsigned long long t = fadd2(fadd2(acc[0], acc[1]),
                                         fadd2(acc[2], acc[3]));
            float2 f = unpack2(t);
            __stcs(dst + r * DH, f.x + f.y + bias);
        }
        p ^= 1;
    }
}

// ---------------------------------------------------------------------------
// Phase 2: sequential scan. 256 blocks x 128 threads, one row per block,
// 2 CTAs/SM.
//
// MIO-pressure layout (the binding pipe per R5-R12 ncu: L1 is always the
// top pipe at ~1.75x fma). Lane pair (2i, 2i+1) jointly owns units
// {2i, 2i+1}:
//   even lane: both units over k in [0,64);  odd lane: k in [64,128)
//   -> per thread: 2 half-rows of W = 128 floats (same 128 regs as before),
//      64 FFMA2 (same fma floor), but only 16 LDS.128 (its 64-float
//      h-slice) instead of 32: LDS:FFMA2 ratio 1:2 -> 1:4.
//   -> ONE shfl.xor(1) completes both units (each lane sends the
//      partner-unit partial, receives its own unit's other half).
// h is stored with the hi half at float-offset 68 (16B pad) so even/odd
// lanes read disjoint banks {4q..} vs {4q+4..}: conflict-free.
// ---------------------------------------------------------------------------
#define HPAD 68                       // padded offset of h[64..127]
#define HBUF_LEN 132                  // 64 + 4 pad + 64

__device__ __forceinline__ int hpos(int k) { return (k < 64) ? k : (k + 4); }

__global__ void __launch_bounds__(128, 2) rnn_scan_kernel(
    const float* __restrict__ Whh,    // [DH, DH]
    float* __restrict__ out)          // [BATCH, DH]
{
    const int t   = threadIdx.x;      // finalizes unit t
    const int odd = t & 1;            // k-half selector
    const int ja  = t & ~1;           // even unit of the lane pair
    const int row = blockIdx.x;
    const int STRIDE = BATCH * DH;

    __shared__ __align__(16) float h0buf[HBUF_LEN];
    __shared__ __align__(16) float h1buf[HBUF_LEN];

    // W slices: rows ja and ja+1, k in [64*odd, 64*odd+64). 32 u64 each.
    unsigned long long wa[32], wb[32];
    {
        const float* ra = Whh + ja * DH + odd * 64;
        const float* rb = ra + DH;
#pragma unroll
        for (int q = 0; q < 16; q++) {
            float4 va = *(const float4*)(ra + q * 4);
            float4 vb = *(const float4*)(rb + q * 4);
            wa[2 * q]     = pack2(va.x, va.y);
            wa[2 * q + 1] = pack2(va.z, va.w);
            wb[2 * q]     = pack2(vb.x, vb.y);
            wb[2 * q + 1] = pack2(vb.z, vb.w);
        }
    }

    h0buf[hpos(t)] = 0.0f;            // h0 = 0

    const float* xcol = &g_xproj[row * DH + t];
    float xc = __ldcs(xcol);
    float xn = __ldcs(xcol + STRIDE);
    const float* xp = xcol + 2 * STRIDE;

    __syncthreads();

    const int hoff = odd * HPAD;      // this lane's 64-float h-slice
    float hn = 0.0f;

#pragma unroll 1
    for (int s = 0; s < SEQ; s += 2) {
#pragma unroll
        for (int half = 0; half < 2; half++) {
            const float* hb = half ? h1buf : h0buf;
            float*       nb = half ? h0buf : h1buf;

            float xf = (s + 2 + half < SEQ) ? __ldcs(xp + half * STRIDE) : 0.0f;

            const ulonglong2* hv = (const ulonglong2*)(hb + hoff);
            unsigned long long aA[4] = {0ULL, 0ULL, 0ULL, 0ULL};
            unsigned long long aB[4] = {0ULL, 0ULL, 0ULL, 0ULL};
#pragma unroll
            for (int q = 0; q < 16; q++) {        // 16 x LDS.128 per thread
                ulonglong2 p = hv[q];
                ffma2(aA[(2 * q)     & 3], wa[2 * q],     p.x);
                ffma2(aA[(2 * q + 1) & 3], wa[2 * q + 1], p.y);
                ffma2(aB[(2 * q)     & 3], wb[2 * q],     p.x);
                ffma2(aB[(2 * q + 1) & 3], wb[2 * q + 1], p.y);
            }
            unsigned long long uA = fadd2(fadd2(aA[0], aA[1]),
                                          fadd2(aA[2], aA[3]));
            unsigned long long uB = fadd2(fadd2(aB[0], aB[1]),
                                          fadd2(aB[2], aB[3]));
            float2 fA = unpack2(uA), fB = unpack2(uB);
            float pa = fA.x + fA.y;               // partial of unit ja
            float pb = fB.x + fB.y;               // partial of unit ja+1

            // Single exchange completes both units: even lane sends its
            // partial of unit ja+1, receives partner's partial of unit ja.
            float send = odd ? pa : pb;
            float recv = __shfl_xor_sync(0xFFFFFFFFu, send, 1);
            float sum  = (odd ? pb : pa) + recv;  // full dot for unit t

            hn = fast_tanh(xc + sum);
            nb[hpos(t)] = hn;

            xc = xn; xn = xf;
            __syncthreads();
        }
        xp += 2 * STRIDE;
    }

    out[row * DH + t] = hn;
}

// ---------------------------------------------------------------------------
// Launch.
// ---------------------------------------------------------------------------
extern "C" void kernel_launch(void* const* d_in, const int* in_sizes, int n_in,
                              void* d_out, int out_size) {
    const float* input = nullptr;
    const float* Wih   = nullptr;
    const float* Whh   = nullptr;
    const float* bA    = nullptr;
    const float* bB    = nullptr;

    for (int i = 0; i < n_in; i++) {
        const int sz = in_sizes[i];
        const float* p = (const float*)d_in[i];
        if      (sz == SEQ * BATCH * DIN) input = p;
        else if (sz == DH * DIN)          Wih   = p;
        else if (sz == DH * DH)           Whh   = p;
        else if (sz == DH)                { if (!bA) bA = p; else bB = p; }
    }

    xproj_kernel<<<2048, 128>>>(input, Wih, bA, bB);
    rnn_scan_kernel<<<BATCH, 128>>>(Whh, (float*)d_out);
}